// round 7
// baseline (speedup 1.0000x reference)
#include <cuda_runtime.h>
#include <cstdint>

// ---------------- problem constants ----------------
#define BATCH 4
#define SEQ 2048
#define EMB 2048
#define NH 16
#define DH 128
#define BH (BATCH * NH)          // 64
#define SD (SEQ * DH)            // 262144
#define SS ((size_t)SEQ * SEQ)

// scratch (allocation-free rule)
__device__ float g_q[(size_t)BH * SD];
__device__ float g_k[(size_t)BH * SD];
__device__ float g_v[(size_t)BH * SD];
__device__ float g_scores[(size_t)BH * SS];
__device__ float g_ctx[(size_t)BATCH * SEQ * EMB];
__device__ float g_xt[(size_t)BATCH * SEQ * EMB];   // tf32-rounded x
__device__ float g_wt[4][(size_t)EMB * EMB];        // tf32-rounded Wq,Wk,Wv,Wo

__device__ __forceinline__ float rtf32(float x) {
    float y;
    asm("cvt.rna.tf32.f32 %0, %1;" : "=f"(y) : "f"(x));
    return y;
}
__device__ __forceinline__ uint32_t smem_u32(const void* p) {
    return (uint32_t)__cvta_generic_to_shared(p);
}
__device__ __forceinline__ void cp16(uint32_t s, const void* g) {
    asm volatile("cp.async.cg.shared.global [%0], [%1], 16;\n" :: "r"(s), "l"(g));
}
__device__ __forceinline__ void ldsm4(uint32_t* r, uint32_t addr) {
    asm volatile("ldmatrix.sync.aligned.m8n8.x4.shared.b16 {%0,%1,%2,%3}, [%4];"
                 : "=r"(r[0]), "=r"(r[1]), "=r"(r[2]), "=r"(r[3]) : "r"(addr));
}
__device__ __forceinline__ void mma_tf32(float* c, const uint32_t* a, const uint32_t* b) {
    asm volatile(
        "mma.sync.aligned.m16n8k8.row.col.f32.tf32.tf32.f32 "
        "{%0,%1,%2,%3},{%4,%5,%6,%7},{%8,%9},{%0,%1,%2,%3};"
        : "+f"(c[0]), "+f"(c[1]), "+f"(c[2]), "+f"(c[3])
        : "r"(a[0]), "r"(a[1]), "r"(a[2]), "r"(a[3]), "r"(b[0]), "r"(b[1]));
}

// ---------------------------------------------------------------------------
// TF32 mma.sync GEMM, CTA 256x128, 256 threads = 8 warps (4m x 2n),
// warp tile 64x64, BK=32, 3-stage cp.async pipeline, ldmatrix operand loads.
// Smem tiles K-contiguous [row][k], stride 36 floats.
// MODE 0: QKV proj   C = x_t * W_t^T, scatter to g_q/g_k/g_v per head (rounded)
// MODE 1: scores     C = Q K^T per (b,h); fully-masked blocks skipped
// MODE 2: ctx        C = P V per (b,h); K truncated causally (V transposed on load)
// MODE 3: out proj   C = ctx * Wo_t^T
// ---------------------------------------------------------------------------
#define BM 256
#define BK 32
#define SA 36                                   // tile row stride in floats
#define B_OFF (BM * SA)                         // words
#define STAGE_WORDS ((BM + 128) * SA)           // 13824 words = 55296 B
#define NSTAGE 3
#define SMEM_BYTES (NSTAGE * STAGE_WORDS * 4)   // 165888

template<int MODE>
__global__ __launch_bounds__(256)
void gemm_tc(const float* __restrict__ Aext, const float* __restrict__ Bext,
             float* __restrict__ Oext, int sel)
{
    if (MODE == 1 && blockIdx.x > 2 * blockIdx.y + 1) return;  // fully-masked causal block

    extern __shared__ float dyn[];

    const int tid  = threadIdx.x;
    const int wid  = tid >> 5;
    const int lane = tid & 31;
    const int wr   = wid >> 1;     // 4 m-groups of 64
    const int wc   = wid & 1;      // 2 n-groups of 64
    const int lq   = lane >> 3;    // ldmatrix quadrant
    const int lr   = lane & 7;
    const int m0   = blockIdx.y * BM;
    const int n0   = blockIdx.x * 128;
    const int z    = blockIdx.z;

    const float* A;  int lda;
    const float* Bm; int ldb;
    int Ktot;
    if (MODE == 0)      { A = Aext;                      lda = EMB; Bm = Bext;                 ldb = EMB; Ktot = EMB; }
    else if (MODE == 1) { A = g_q + (size_t)z * SD;      lda = DH;  Bm = g_k + (size_t)z * SD; ldb = DH;  Ktot = DH; }
    else if (MODE == 2) { A = g_scores + (size_t)z * SS; lda = SEQ; Bm = g_v + (size_t)z * SD; ldb = DH;  Ktot = m0 + BM; }
    else                { A = g_ctx;                     lda = EMB; Bm = Bext;                 ldb = EMB; Ktot = EMB; }
    const int T = Ktot / BK;

    const uint32_t sbase = smem_u32(dyn);

    auto load_stage = [&](int buf, int t) {
        const int k0 = t * BK;
        const uint32_t sa = sbase + (uint32_t)(buf * STAGE_WORDS) * 4u;
        // A: 256 rows x 32 k (2048 chunks of 16B, 8/thread)
        #pragma unroll
        for (int i = 0; i < 8; i++) {
            int id = tid + i * 256;
            int r = id >> 3, c4 = id & 7;
            cp16(sa + (uint32_t)(r * SA + c4 * 4) * 4u,
                 A + (size_t)(m0 + r) * lda + k0 + c4 * 4);
        }
        if (MODE != 2) {
            // B rows are N-dim, K contiguous (1024 chunks, 4/thread)
            #pragma unroll
            for (int i = 0; i < 4; i++) {
                int id = tid + i * 256;
                int r = id >> 3, c4 = id & 7;
                cp16(sa + (uint32_t)(B_OFF + r * SA + c4 * 4) * 4u,
                     Bm + (size_t)(n0 + r) * ldb + k0 + c4 * 4);
            }
        } else {
            // V [k][128] row-major -> transpose into Bs[n][k]
            float* bp = dyn + buf * STAGE_WORDS + B_OFF;
            #pragma unroll
            for (int i = 0; i < 4; i++) {
                int id = tid + i * 256;          // 0..1023
                int n4 = id & 31, k = id >> 5;   // n4: float4 group, k: 0..31
                float4 v = *(const float4*)(Bm + (size_t)(k0 + k) * DH + n4 * 4);
                bp[(n4 * 4 + 0) * SA + k] = v.x;
                bp[(n4 * 4 + 1) * SA + k] = v.y;
                bp[(n4 * 4 + 2) * SA + k] = v.z;
                bp[(n4 * 4 + 3) * SA + k] = v.w;
            }
        }
        asm volatile("cp.async.commit_group;\n");
    };

    float acc[4][8][4];
    #pragma unroll
    for (int i = 0; i < 4; i++)
        #pragma unroll
        for (int j = 0; j < 8; j++)
            #pragma unroll
            for (int e = 0; e < 4; e++) acc[i][j][e] = 0.0f;

    load_stage(0, 0);
    load_stage(1, 1);

    // ldmatrix addressing
    const int a_row = wr * 64 + (lq & 1) * 8 + lr;
    const int a_kq  = (lq >> 1) * 4;
    const int b_row = wc * 64 + (lq >> 1) * 8 + lr;
    const int b_kq  = (lq & 1) * 4;

    for (int t = 0; t < T; t++) {
        asm volatile("cp.async.wait_group 1;\n" ::: "memory");
        __syncthreads();

        if (t + 2 < T) load_stage((t + 2) % NSTAGE, t + 2);
        else asm volatile("cp.async.commit_group;\n");

        const uint32_t st = sbase + (uint32_t)((t % NSTAGE) * STAGE_WORDS) * 4u;

        #pragma unroll
        for (int ks = 0; ks < 4; ks++) {
            uint32_t a[4][4], b[8][2];
            #pragma unroll
            for (int i = 0; i < 4; i++)
                ldsm4(a[i], st + (uint32_t)((a_row + i * 16) * SA + ks * 8 + a_kq) * 4u);
            #pragma unroll
            for (int u = 0; u < 4; u++) {
                uint32_t r[4];
                ldsm4(r, st + (uint32_t)(B_OFF + (b_row + u * 16) * SA + ks * 8 + b_kq) * 4u);
                b[2 * u][0] = r[0]; b[2 * u][1] = r[1];
                b[2 * u + 1][0] = r[2]; b[2 * u + 1][1] = r[3];
            }
            #pragma unroll
            for (int i = 0; i < 4; i++)
                #pragma unroll
                for (int j = 0; j < 8; j++)
                    mma_tf32(acc[i][j], a[i], b[j]);
        }
    }

    // ---- epilogue ----
    float* base; size_t ldo;
    bool do_round;
    if (MODE == 0) {
        int b = m0 >> 11;
        float* qkv = (sel == 0 ? g_q : sel == 1 ? g_k : g_v);
        base = qkv + ((size_t)(b * NH + blockIdx.x)) * SD + (size_t)(m0 & (SEQ - 1)) * DH;
        ldo = DH;  do_round = true;
    } else if (MODE == 1) {
        base = g_scores + (size_t)z * SS + (size_t)m0 * SEQ + n0;
        ldo = SEQ; do_round = false;
    } else if (MODE == 2) {
        int b = z >> 4, h = z & 15;
        base = g_ctx + (size_t)b * SEQ * EMB + (size_t)m0 * EMB + h * DH;
        ldo = EMB; do_round = true;
    } else {
        base = Oext + (size_t)m0 * EMB + n0;
        ldo = EMB; do_round = false;
    }

    const int er = lane >> 2;            // 0..7
    const int ec = (lane & 3) * 2;
    #pragma unroll
    for (int i = 0; i < 4; i++)
        #pragma unroll
        for (int j = 0; j < 8; j++) {
            int lrow = wr * 64 + i * 16 + er;
            int lcol = wc * 64 + j * 8 + ec;
            float2 v0, v1;
            if (do_round) {
                v0 = make_float2(rtf32(acc[i][j][0]), rtf32(acc[i][j][1]));
                v1 = make_float2(rtf32(acc[i][j][2]), rtf32(acc[i][j][3]));
            } else {
                v0 = make_float2(acc[i][j][0], acc[i][j][1]);
                v1 = make_float2(acc[i][j][2], acc[i][j][3]);
            }
            *(float2*)(base + (size_t)lrow * ldo + lcol) = v0;
            *(float2*)(base + (size_t)(lrow + 8) * ldo + lcol) = v1;
        }
}

// ---------------------------------------------------------------------------
// causal row softmax, in place; zero-fill to the 256-aligned frontier
// ---------------------------------------------------------------------------
__global__ __launch_bounds__(256)
void softmax_causal()
{
    const int q  = blockIdx.x;
    const int bh = blockIdx.y;
    float* row = g_scores + (size_t)bh * SS + (size_t)q * SEQ;
    const float inv = 0.08838834764831845f;   // 1/sqrt(128)
    const int n = q + 1;
    const int lim = ((q >> 8) + 1) << 8;      // 256-aligned frontier
    const int t = threadIdx.x;

    float vals[8];
    float m = -1e30f;
    #pragma unroll
    for (int i = 0; i < 8; i++) {
        int idx = t + i * 256;
        float v = (idx < n) ? row[idx] : -1e30f;
        vals[i] = v;
        m = fmaxf(m, v);
    }
    __shared__ float red[256];
    red[t] = m; __syncthreads();
    #pragma unroll
    for (int s = 128; s > 0; s >>= 1) {
        if (t < s) red[t] = fmaxf(red[t], red[t + s]);
        __syncthreads();
    }
    m = red[0];
    __syncthreads();

    float sum = 0.0f;
    #pragma unroll
    for (int i = 0; i < 8; i++) {
        int idx = t + i * 256;
        if (idx < n) {
            float p = __expf((vals[i] - m) * inv);
            vals[i] = p;
            sum += p;
        }
    }
    red[t] = sum; __syncthreads();
    #pragma unroll
    for (int s = 128; s > 0; s >>= 1) {
        if (t < s) red[t] += red[t + s];
        __syncthreads();
    }
    const float rs = 1.0f / red[0];

    #pragma unroll
    for (int i = 0; i < 8; i++) {
        int idx = t + i * 256;
        if (idx < lim) row[idx] = (idx < n) ? rtf32(vals[i] * rs) : 0.0f;
    }
}

// elementwise tf32 rounding pre-pass (float4)
__global__ void round_pass(const float4* __restrict__ in, float4* __restrict__ out, int n4)
{
    int i = blockIdx.x * blockDim.x + threadIdx.x;
    if (i < n4) {
        float4 v = in[i];
        v.x = rtf32(v.x); v.y = rtf32(v.y); v.z = rtf32(v.z); v.w = rtf32(v.w);
        out[i] = v;
    }
}

__global__ void add_bias(float* __restrict__ out, const float* __restrict__ bo)
{
    size_t i = (size_t)blockIdx.x * blockDim.x + threadIdx.x;
    if (i < (size_t)BATCH * SEQ * EMB) out[i] += bo[i & (EMB - 1)];
}

extern "C" void kernel_launch(void* const* d_in, const int* in_sizes, int n_in,
                              void* d_out, int out_size)
{
    const float* x  = (const float*)d_in[0];
    const float* W[4] = {(const float*)d_in[1], (const float*)d_in[2],
                         (const float*)d_in[3], (const float*)d_in[4]};
    const float* bo = (const float*)d_in[5];
    float* out = (float*)d_out;

    cudaFuncSetAttribute(gemm_tc<0>, cudaFuncAttributeMaxDynamicSharedMemorySize, SMEM_BYTES);
    cudaFuncSetAttribute(gemm_tc<1>, cudaFuncAttributeMaxDynamicSharedMemorySize, SMEM_BYTES);
    cudaFuncSetAttribute(gemm_tc<2>, cudaFuncAttributeMaxDynamicSharedMemorySize, SMEM_BYTES);
    cudaFuncSetAttribute(gemm_tc<3>, cudaFuncAttributeMaxDynamicSharedMemorySize, SMEM_BYTES);

    float *xt, *wt;
    cudaGetSymbolAddress((void**)&xt, g_xt);
    cudaGetSymbolAddress((void**)&wt, g_wt);

    dim3 blk(256);
    const int XN4 = BATCH * SEQ * EMB / 4;
    const int WN4 = EMB * EMB / 4;

    round_pass<<<(XN4 + 255) / 256, 256>>>((const float4*)x, (float4*)xt, XN4);
    for (int i = 0; i < 4; i++)
        round_pass<<<(WN4 + 255) / 256, 256>>>((const float4*)W[i],
                                               (float4*)(wt + (size_t)i * EMB * EMB), WN4);

    // QKV projections: M=8192 (32 tiles of 256), N=2048 (16 tiles = heads)
    gemm_tc<0><<<dim3(16, 32, 1), blk, SMEM_BYTES>>>(xt, wt + 0 * (size_t)EMB * EMB, nullptr, 0);
    gemm_tc<0><<<dim3(16, 32, 1), blk, SMEM_BYTES>>>(xt, wt + 1 * (size_t)EMB * EMB, nullptr, 1);
    gemm_tc<0><<<dim3(16, 32, 1), blk, SMEM_BYTES>>>(xt, wt + 2 * (size_t)EMB * EMB, nullptr, 2);

    // scores = Q K^T per (b,h); fully-masked blocks skipped
    gemm_tc<1><<<dim3(16, 8, BH), blk, SMEM_BYTES>>>(nullptr, nullptr, nullptr, 0);

    // causal softmax (scale folded in), in place
    softmax_causal<<<dim3(SEQ, BH), 256>>>();

    // ctx = P V per (b,h); K truncated causally
    gemm_tc<2><<<dim3(1, 8, BH), blk, SMEM_BYTES>>>(nullptr, nullptr, nullptr, 0);

    // out = ctx Wo^T
    gemm_tc<3><<<dim3(16, 32, 1), blk, SMEM_BYTES>>>(nullptr, wt + 3 * (size_t)EMB * EMB, out, 0);

    add_bias<<<(BATCH * SEQ * EMB + 511) / 512, 512>>>(out, bo);
}

// round 8
// speedup vs baseline: 1.1619x; 1.1619x over previous
#include <cuda_runtime.h>
#include <cstdint>

// ---------------- problem constants ----------------
#define BATCH 4
#define SEQ 2048
#define EMB 2048
#define NH 16
#define DH 128
#define BH (BATCH * NH)          // 64
#define SD (SEQ * DH)            // 262144
#define SS ((size_t)SEQ * SEQ)
#define INVSQ 0.08838834764831845f   // 1/sqrt(128)

// scratch (allocation-free rule)
__device__ float g_q[(size_t)BH * SD];
__device__ float g_k[(size_t)BH * SD];
__device__ float g_v[(size_t)BH * SD];
__device__ float g_scores[(size_t)BH * SS];
__device__ float g_ctx[(size_t)BATCH * SEQ * EMB];
__device__ float g_xt[(size_t)BATCH * SEQ * EMB];   // tf32-rounded x
__device__ float g_wt[4][(size_t)EMB * EMB];        // tf32-rounded Wq,Wk,Wv,Wo
__device__ float g_m[(size_t)BH * SEQ];             // per-row max
__device__ float g_l[(size_t)BH * SEQ];             // per-row exp-sum

__device__ __forceinline__ float rtf32(float x) {
    float y;
    asm("cvt.rna.tf32.f32 %0, %1;" : "=f"(y) : "f"(x));
    return y;
}
__device__ __forceinline__ uint32_t smem_u32(const void* p) {
    return (uint32_t)__cvta_generic_to_shared(p);
}
__device__ __forceinline__ void cp16(uint32_t s, const void* g) {
    asm volatile("cp.async.cg.shared.global [%0], [%1], 16;\n" :: "r"(s), "l"(g));
}
__device__ __forceinline__ void ldsm4(uint32_t* r, uint32_t addr) {
    asm volatile("ldmatrix.sync.aligned.m8n8.x4.shared.b16 {%0,%1,%2,%3}, [%4];"
                 : "=r"(r[0]), "=r"(r[1]), "=r"(r[2]), "=r"(r[3]) : "r"(addr));
}
__device__ __forceinline__ void mma_tf32(float* c, const uint32_t* a, const uint32_t* b) {
    asm volatile(
        "mma.sync.aligned.m16n8k8.row.col.f32.tf32.tf32.f32 "
        "{%0,%1,%2,%3},{%4,%5,%6,%7},{%8,%9},{%0,%1,%2,%3};"
        : "+f"(c[0]), "+f"(c[1]), "+f"(c[2]), "+f"(c[3])
        : "r"(a[0]), "r"(a[1]), "r"(a[2]), "r"(a[3]), "r"(b[0]), "r"(b[1]));
}

// ---------------------------------------------------------------------------
// TF32 mma.sync GEMM, CTA 128x128, 256 threads = 8 warps (4m x 2n),
// warp tile 32x64, BK=32, 3-stage cp.async pipeline, ldmatrix operand loads.
// Smem tiles K-contiguous [row][k], stride 36 floats.
// MODE 0: QKV proj   C = x_t * W_t^T, scatter to g_q/g_k/g_v per head (rounded)
// MODE 1: scores     C = Q K^T per (b,h), raw; blocks above diagonal skipped
// MODE 2: ctx        C = softmax(S) V per (b,h); exp applied in-smem to each
//                    A-tile (stats from g_m/g_l), K truncated causally
// MODE 3: out proj   C = ctx * Wo_t^T + bias
// ---------------------------------------------------------------------------
#define BK 32
#define SA 36                                  // tile row stride in floats
#define B_OFF (128 * SA)                       // words
#define STAGE_WORDS (2 * 128 * SA)             // 9216 words = 36864 B
#define NSTAGE 3
#define STAT_OFF (NSTAGE * STAGE_WORDS)        // words: [m:128][rl:128]
#define SMEM_BYTES ((STAT_OFF + 256) * 4)      // 111616

template<int MODE>
__global__ __launch_bounds__(256)
void gemm_tc(const float* __restrict__ Aext, const float* __restrict__ Bext,
             float* __restrict__ Oext, const float* __restrict__ bias, int sel)
{
    if (MODE == 1 && blockIdx.x > blockIdx.y) return;   // fully-masked causal block

    extern __shared__ float dyn[];

    const int tid  = threadIdx.x;
    const int wid  = tid >> 5;
    const int lane = tid & 31;
    const int wr   = wid >> 1;     // 4 m-groups of 32
    const int wc   = wid & 1;      // 2 n-groups of 64
    const int lq   = lane >> 3;    // ldmatrix quadrant
    const int lr   = lane & 7;
    const int m0   = blockIdx.y * 128;
    const int n0   = blockIdx.x * 128;
    const int z    = blockIdx.z;

    const float* A;  int lda;
    const float* Bm; int ldb;
    int Ktot;
    if (MODE == 0)      { A = Aext;                      lda = EMB; Bm = Bext;                 ldb = EMB; Ktot = EMB; }
    else if (MODE == 1) { A = g_q + (size_t)z * SD;      lda = DH;  Bm = g_k + (size_t)z * SD; ldb = DH;  Ktot = DH; }
    else if (MODE == 2) { A = g_scores + (size_t)z * SS; lda = SEQ; Bm = g_v + (size_t)z * SD; ldb = DH;  Ktot = m0 + 128; }
    else                { A = g_ctx;                     lda = EMB; Bm = Bext;                 ldb = EMB; Ktot = EMB; }
    const int T = Ktot / BK;

    const uint32_t sbase = smem_u32(dyn);

    // MODE2: cache per-row softmax stats in smem (visible after first syncthreads)
    if (MODE == 2 && tid < 128) {
        float mv = g_m[(size_t)z * SEQ + m0 + tid];
        float lv = g_l[(size_t)z * SEQ + m0 + tid];
        dyn[STAT_OFF + tid] = mv;
        dyn[STAT_OFF + 128 + tid] = 1.0f / lv;
    }

    auto load_stage = [&](int buf, int t) {
        const int k0 = t * BK;
        const uint32_t sa = sbase + (uint32_t)(buf * STAGE_WORDS) * 4u;
        // A: 128 rows x 32 k (1024 chunks of 16B, 4/thread)
        #pragma unroll
        for (int i = 0; i < 4; i++) {
            int id = tid + i * 256;
            int r = id >> 3, c4 = id & 7;
            cp16(sa + (uint32_t)(r * SA + c4 * 4) * 4u,
                 A + (size_t)(m0 + r) * lda + k0 + c4 * 4);
        }
        if (MODE != 2) {
            // B rows are N-dim, K contiguous
            #pragma unroll
            for (int i = 0; i < 4; i++) {
                int id = tid + i * 256;
                int r = id >> 3, c4 = id & 7;
                cp16(sa + (uint32_t)(B_OFF + r * SA + c4 * 4) * 4u,
                     Bm + (size_t)(n0 + r) * ldb + k0 + c4 * 4);
            }
        } else {
            // V [k][128] row-major -> transpose into Bs[n][k]
            float* bp = dyn + buf * STAGE_WORDS + B_OFF;
            #pragma unroll
            for (int i = 0; i < 4; i++) {
                int id = tid + i * 256;          // 0..1023
                int n4 = id & 31, k = id >> 5;   // n4: float4 group, k: 0..31
                float4 v = *(const float4*)(Bm + (size_t)(k0 + k) * DH + n4 * 4);
                bp[(n4 * 4 + 0) * SA + k] = v.x;
                bp[(n4 * 4 + 1) * SA + k] = v.y;
                bp[(n4 * 4 + 2) * SA + k] = v.z;
                bp[(n4 * 4 + 3) * SA + k] = v.w;
            }
        }
        asm volatile("cp.async.commit_group;\n");
    };

    float acc[2][8][4];
    #pragma unroll
    for (int i = 0; i < 2; i++)
        #pragma unroll
        for (int j = 0; j < 8; j++)
            #pragma unroll
            for (int e = 0; e < 4; e++) acc[i][j][e] = 0.0f;

    load_stage(0, 0);
    load_stage(1, 1);

    // ldmatrix addressing
    const int a_row = wr * 32 + (lq & 1) * 8 + lr;
    const int a_kq  = (lq >> 1) * 4;
    const int b_row = wc * 64 + (lq >> 1) * 8 + lr;
    const int b_kq  = (lq & 1) * 4;

    for (int t = 0; t < T; t++) {
        asm volatile("cp.async.wait_group 1;\n" ::: "memory");
        __syncthreads();

        if (t + 2 < T) load_stage((t + 2) % NSTAGE, t + 2);
        else asm volatile("cp.async.commit_group;\n");

        if (MODE == 2) {
            // in-smem transform of the A tile: raw scores -> tf32 probs
            float* ap = dyn + (t % NSTAGE) * STAGE_WORDS;
            const int k0t = t * BK;
            #pragma unroll
            for (int i = 0; i < 4; i++) {
                int id = tid + i * 256;
                int r = id >> 3, c = (id & 7) * 4;
                int grow = m0 + r;
                float mv = dyn[STAT_OFF + r];
                float rl = dyn[STAT_OFF + 128 + r];
                float4 v = *(float4*)(ap + r * SA + c);
                int gc = k0t + c;
                v.x = (gc + 0 <= grow) ? rtf32(__expf((v.x - mv) * INVSQ) * rl) : 0.0f;
                v.y = (gc + 1 <= grow) ? rtf32(__expf((v.y - mv) * INVSQ) * rl) : 0.0f;
                v.z = (gc + 2 <= grow) ? rtf32(__expf((v.z - mv) * INVSQ) * rl) : 0.0f;
                v.w = (gc + 3 <= grow) ? rtf32(__expf((v.w - mv) * INVSQ) * rl) : 0.0f;
                *(float4*)(ap + r * SA + c) = v;
            }
            __syncthreads();
        }

        const uint32_t st = sbase + (uint32_t)((t % NSTAGE) * STAGE_WORDS) * 4u;

        #pragma unroll
        for (int ks = 0; ks < 4; ks++) {
            uint32_t a[2][4], b[8][2];
            #pragma unroll
            for (int i = 0; i < 2; i++)
                ldsm4(a[i], st + (uint32_t)((a_row + i * 16) * SA + ks * 8 + a_kq) * 4u);
            #pragma unroll
            for (int u = 0; u < 4; u++) {
                uint32_t r[4];
                ldsm4(r, st + (uint32_t)(B_OFF + (b_row + u * 16) * SA + ks * 8 + b_kq) * 4u);
                b[2 * u][0] = r[0]; b[2 * u][1] = r[1];
                b[2 * u + 1][0] = r[2]; b[2 * u + 1][1] = r[3];
            }
            #pragma unroll
            for (int i = 0; i < 2; i++)
                #pragma unroll
                for (int j = 0; j < 8; j++)
                    mma_tf32(acc[i][j], a[i], b[j]);
        }
    }

    // ---- epilogue ----
    float* base; size_t ldo;
    bool do_round;
    if (MODE == 0) {
        int b = m0 >> 11;
        float* qkv = (sel == 0 ? g_q : sel == 1 ? g_k : g_v);
        base = qkv + ((size_t)(b * NH + blockIdx.x)) * SD + (size_t)(m0 & (SEQ - 1)) * DH;
        ldo = DH;  do_round = true;
    } else if (MODE == 1) {
        base = g_scores + (size_t)z * SS + (size_t)m0 * SEQ + n0;
        ldo = SEQ; do_round = false;
    } else if (MODE == 2) {
        int b = z >> 4, h = z & 15;
        base = g_ctx + (size_t)b * SEQ * EMB + (size_t)m0 * EMB + h * DH;
        ldo = EMB; do_round = true;
    } else {
        base = Oext + (size_t)m0 * EMB + n0;
        ldo = EMB; do_round = false;
    }

    const int er = lane >> 2;            // 0..7
    const int ec = (lane & 3) * 2;
    #pragma unroll
    for (int i = 0; i < 2; i++)
        #pragma unroll
        for (int j = 0; j < 8; j++) {
            int lrow = wr * 32 + i * 16 + er;
            int lcol = wc * 64 + j * 8 + ec;
            float2 v0, v1;
            if (do_round) {
                v0 = make_float2(rtf32(acc[i][j][0]), rtf32(acc[i][j][1]));
                v1 = make_float2(rtf32(acc[i][j][2]), rtf32(acc[i][j][3]));
            } else {
                v0 = make_float2(acc[i][j][0], acc[i][j][1]);
                v1 = make_float2(acc[i][j][2], acc[i][j][3]);
            }
            if (MODE == 3) {
                float b0 = bias[n0 + lcol], b1 = bias[n0 + lcol + 1];
                v0.x += b0; v0.y += b1; v1.x += b0; v1.y += b1;
            }
            *(float2*)(base + (size_t)lrow * ldo + lcol) = v0;
            *(float2*)(base + (size_t)(lrow + 8) * ldo + lcol) = v1;
        }
}

// ---------------------------------------------------------------------------
// causal softmax stats: per (bh,row) running max m and exp-sum l.
// One warp per row, 8 rows per 256-thread block.
// ---------------------------------------------------------------------------
__global__ __launch_bounds__(256)
void stats_causal()
{
    const int w    = threadIdx.x >> 5;
    const int lane = threadIdx.x & 31;
    const int q    = blockIdx.x * 8 + w;
    const int bh   = blockIdx.y;
    const float* row = g_scores + (size_t)bh * SS + (size_t)q * SEQ;
    const int n = q + 1;

    float m = -1e30f;
    for (int i4 = lane; i4 * 4 < n; i4 += 32) {
        float4 v = *(const float4*)(row + i4 * 4);
        int c = i4 * 4;
        if (c + 0 < n) m = fmaxf(m, v.x);
        if (c + 1 < n) m = fmaxf(m, v.y);
        if (c + 2 < n) m = fmaxf(m, v.z);
        if (c + 3 < n) m = fmaxf(m, v.w);
    }
    #pragma unroll
    for (int s = 16; s > 0; s >>= 1) m = fmaxf(m, __shfl_xor_sync(0xFFFFFFFFu, m, s));

    float l = 0.0f;
    for (int i4 = lane; i4 * 4 < n; i4 += 32) {
        float4 v = *(const float4*)(row + i4 * 4);
        int c = i4 * 4;
        if (c + 0 < n) l += __expf((v.x - m) * INVSQ);
        if (c + 1 < n) l += __expf((v.y - m) * INVSQ);
        if (c + 2 < n) l += __expf((v.z - m) * INVSQ);
        if (c + 3 < n) l += __expf((v.w - m) * INVSQ);
    }
    #pragma unroll
    for (int s = 16; s > 0; s >>= 1) l += __shfl_xor_sync(0xFFFFFFFFu, l, s);

    if (lane == 0) {
        g_m[(size_t)bh * SEQ + q] = m;
        g_l[(size_t)bh * SEQ + q] = l;
    }
}

// elementwise tf32 rounding pre-pass (float4)
__global__ void round_pass(const float4* __restrict__ in, float4* __restrict__ out, int n4)
{
    int i = blockIdx.x * blockDim.x + threadIdx.x;
    if (i < n4) {
        float4 v = in[i];
        v.x = rtf32(v.x); v.y = rtf32(v.y); v.z = rtf32(v.z); v.w = rtf32(v.w);
        out[i] = v;
    }
}

extern "C" void kernel_launch(void* const* d_in, const int* in_sizes, int n_in,
                              void* d_out, int out_size)
{
    const float* x  = (const float*)d_in[0];
    const float* W[4] = {(const float*)d_in[1], (const float*)d_in[2],
                         (const float*)d_in[3], (const float*)d_in[4]};
    const float* bo = (const float*)d_in[5];
    float* out = (float*)d_out;

    cudaFuncSetAttribute(gemm_tc<0>, cudaFuncAttributeMaxDynamicSharedMemorySize, SMEM_BYTES);
    cudaFuncSetAttribute(gemm_tc<1>, cudaFuncAttributeMaxDynamicSharedMemorySize, SMEM_BYTES);
    cudaFuncSetAttribute(gemm_tc<2>, cudaFuncAttributeMaxDynamicSharedMemorySize, SMEM_BYTES);
    cudaFuncSetAttribute(gemm_tc<3>, cudaFuncAttributeMaxDynamicSharedMemorySize, SMEM_BYTES);

    float *xt, *wt;
    cudaGetSymbolAddress((void**)&xt, g_xt);
    cudaGetSymbolAddress((void**)&wt, g_wt);

    dim3 blk(256);
    const int XN4 = BATCH * SEQ * EMB / 4;
    const int WN4 = EMB * EMB / 4;

    round_pass<<<(XN4 + 255) / 256, 256>>>((const float4*)x, (float4*)xt, XN4);
    for (int i = 0; i < 4; i++)
        round_pass<<<(WN4 + 255) / 256, 256>>>((const float4*)W[i],
                                               (float4*)(wt + (size_t)i * EMB * EMB), WN4);

    // QKV projections: M=8192 (64 tiles), N=2048 (16 tiles = heads)
    gemm_tc<0><<<dim3(16, 64, 1), blk, SMEM_BYTES>>>(xt, wt + 0 * (size_t)EMB * EMB, nullptr, nullptr, 0);
    gemm_tc<0><<<dim3(16, 64, 1), blk, SMEM_BYTES>>>(xt, wt + 1 * (size_t)EMB * EMB, nullptr, nullptr, 1);
    gemm_tc<0><<<dim3(16, 64, 1), blk, SMEM_BYTES>>>(xt, wt + 2 * (size_t)EMB * EMB, nullptr, nullptr, 2);

    // scores = Q K^T per (b,h), raw; above-diagonal blocks skipped
    gemm_tc<1><<<dim3(16, 16, BH), blk, SMEM_BYTES>>>(nullptr, nullptr, nullptr, nullptr, 0);

    // softmax stats (max + exp-sum per row)
    stats_causal<<<dim3(SEQ / 8, BH), 256>>>();

    // ctx = softmax(S) V per (b,h); exp applied in-smem, K truncated causally
    gemm_tc<2><<<dim3(1, 16, BH), blk, SMEM_BYTES>>>(nullptr, nullptr, nullptr, nullptr, 0);

    // out = ctx Wo^T + bias
    gemm_tc<3><<<dim3(16, 64, 1), blk, SMEM_BYTES>>>(nullptr, wt + 3 * (size_t)EMB * EMB, out, bo, 0);
}